// round 1
// baseline (speedup 1.0000x reference)
#include <cuda_runtime.h>

#define BB 32
#define CC 256
#define PP 32
#define HWD 3136
#define NCH 7
#define CHUNK 448      // HWD / NCH
#define KT 32
#define NKT 14         // CHUNK / KT
#define CT 128         // c tile
#define NCT 2          // CC / CT
#define PS 36          // padded smem k-stride (32 + 4): conflict-free, 16B-multiple rows
#define NTHREADS 128

__device__ float g_part[NCH * BB * PP * CC];   // 7.34 MB partial sums

#define FMA2(d, a, b) asm("fma.rn.f32x2 %0, %1, %2, %0;" : "+l"(d) : "l"(a), "l"(b))

__global__ __launch_bounds__(NTHREADS)
void rfe_main_kernel(const float* __restrict__ x,
                     const float* __restrict__ pa,
                     const float* __restrict__ conv_w,
                     const float* __restrict__ conv_b)
{
    __shared__ __align__(16) float pa_s[PP][PS];
    __shared__ __align__(16) float x_s[CT][PS];
    __shared__ float w_s[PP];

    const int tid   = threadIdx.x;
    const int chunk = blockIdx.x;   // 0..6
    const int ct    = blockIdx.y;   // 0..1
    const int b     = blockIdx.z;   // 0..31
    const int hw0   = chunk * CHUNK;

    if (tid < PP) w_s[tid] = conv_w[tid];
    const float bias = conv_b[0];

    // --- gmem load mapping: 8 float4 per row of KT floats ---
    const int kq  = tid & 7;   // which float4 in the k-tile
    const int row = tid >> 3;  // 0..15
    const float* xg = x  + ((size_t)b * CC + (size_t)ct * CT) * HWD + hw0 + kq * 4;
    const float* pg = pa + ((size_t)b * PP) * HWD + hw0 + kq * 4;

    // --- compute mapping: 4 p-groups x 32 c-groups; tile 8p x 4c interleaved ---
    const int p_idx = tid >> 5;   // 0..3  (constant within a warp -> pa broadcast)
    const int c_idx = tid & 31;   // 0..31

    unsigned long long acc[8][4];
    #pragma unroll
    for (int i = 0; i < 8; ++i)
        #pragma unroll
        for (int j = 0; j < 4; ++j)
            acc[i][j] = 0ull;   // (0.f, 0.f) packed

    for (int t = 0; t < NKT; ++t) {
        const int kbase = t * KT;
        __syncthreads();   // previous tile's smem fully consumed

        // load pa tile [32 p][32 k], k-major (coalesced, no transpose)
        #pragma unroll
        for (int r = 0; r < 2; ++r) {
            const int p = row + 16 * r;
            float4 v = *(const float4*)(pg + (size_t)p * HWD + kbase);
            *(float4*)&pa_s[p][kq * 4] = v;
        }
        // load x tile [128 c][32 k]
        #pragma unroll
        for (int r = 0; r < 8; ++r) {
            const int c = row + 16 * r;
            float4 v = *(const float4*)(xg + (size_t)c * HWD + kbase);
            *(float4*)&x_s[c][kq * 4] = v;
        }
        __syncthreads();

        // warp 0: compute att[k] = sigmoid(w . pa[:,k] + bias), fold into pa rows
        if (tid < KT) {
            const int k = tid;
            float z = bias;
            #pragma unroll
            for (int p = 0; p < PP; ++p) z += pa_s[p][k] * w_s[p];
            const float att = 1.f / (1.f + expf(-z));
            #pragma unroll
            for (int p = 0; p < PP; ++p) pa_s[p][k] *= att;
        }
        __syncthreads();

        // GEMM: acc[p,c] += pa'[p,k] * x[c,k], packed over k-pairs (fma.rn.f32x2)
        #pragma unroll
        for (int k = 0; k < KT; k += 4) {
            ulonglong2 xv[4];
            #pragma unroll
            for (int j = 0; j < 4; ++j)
                xv[j] = *(const ulonglong2*)&x_s[c_idx + 32 * j][k];
            #pragma unroll
            for (int i = 0; i < 8; ++i) {
                const ulonglong2 av = *(const ulonglong2*)&pa_s[p_idx + 4 * i][k];
                #pragma unroll
                for (int j = 0; j < 4; ++j) {
                    FMA2(acc[i][j], av.x, xv[j].x);
                    FMA2(acc[i][j], av.y, xv[j].y);
                }
            }
        }
    }

    // write partial [chunk][b][p][c]
    float* outp = g_part + ((size_t)chunk * BB + b) * (PP * CC);
    #pragma unroll
    for (int i = 0; i < 8; ++i) {
        const int p = p_idx + 4 * i;
        #pragma unroll
        for (int j = 0; j < 4; ++j) {
            const int c = ct * CT + c_idx + 32 * j;
            const unsigned long long v = acc[i][j];
            const float lo = __uint_as_float((unsigned)(v & 0xffffffffull));
            const float hi = __uint_as_float((unsigned)(v >> 32));
            outp[p * CC + c] = lo + hi;
        }
    }
}

__global__ void rfe_reduce_kernel(float* __restrict__ out)
{
    const int idx = blockIdx.x * blockDim.x + threadIdx.x;  // 0..262143
    float s = 0.f;
    #pragma unroll
    for (int ch = 0; ch < NCH; ++ch)
        s += g_part[(size_t)ch * (BB * PP * CC) + idx];
    out[idx] = s;
}

extern "C" void kernel_launch(void* const* d_in, const int* in_sizes, int n_in,
                              void* d_out, int out_size)
{
    const float* x      = (const float*)d_in[0];  // [32,256,56,56]
    const float* pa     = (const float*)d_in[1];  // [32,32,56,56]
    const float* conv_w = (const float*)d_in[2];  // [32]
    const float* conv_b = (const float*)d_in[3];  // [1]
    float* out = (float*)d_out;                   // [32, 8192]

    dim3 grid(NCH, NCT, BB);
    rfe_main_kernel<<<grid, NTHREADS>>>(x, pa, conv_w, conv_b);
    rfe_reduce_kernel<<<(BB * PP * CC) / 256, 256>>>(out);
}

// round 3
// speedup vs baseline: 1.0390x; 1.0390x over previous
#include <cuda_runtime.h>
#include <cstdint>

#define BB 32
#define CC 256
#define PP 32
#define HWD 3136
#define NCH 7
#define CHUNK 448      // HWD / NCH
#define KT 32
#define NKT 14         // CHUNK / KT
#define CT 128         // c tile
#define NCT 2          // CC / CT
#define PS 36          // padded smem k-stride (32+4): conflict-free, 16B-multiple rows
#define NTHREADS 128

__device__ float g_part[NCH * BB * PP * CC];   // 7.34 MB partial sums
__device__ float g_att[BB * HWD];              // 0.4 MB sigmoid gate

#define FMA2(d, a, b) asm("fma.rn.f32x2 %0, %1, %2, %0;" : "+l"(d) : "l"(a), "l"(b))

__device__ __forceinline__ void cpasync16(uint32_t s, const void* g) {
    asm volatile("cp.async.cg.shared.global [%0], [%1], 16;\n" :: "r"(s), "l"(g));
}
__device__ __forceinline__ void cpcommit() {
    asm volatile("cp.async.commit_group;\n" ::: "memory");
}
template <int N>
__device__ __forceinline__ void cpwait() {
    asm volatile("cp.async.wait_group %0;\n" :: "n"(N) : "memory");
}

// ---------------- att = sigmoid(w . pa + bias) ----------------
__global__ __launch_bounds__(256)
void rfe_att_kernel(const float* __restrict__ pa,
                    const float* __restrict__ conv_w,
                    const float* __restrict__ conv_b)
{
    __shared__ float w_s[PP];
    if (threadIdx.x < PP) w_s[threadIdx.x] = conv_w[threadIdx.x];
    __syncthreads();
    const int idx = blockIdx.x * 256 + threadIdx.x;    // 0..B*HWD-1 (exact)
    const int b  = idx / HWD;
    const int hw = idx - b * HWD;
    const float* pp = pa + (size_t)b * PP * HWD + hw;
    float z = conv_b[0];
    #pragma unroll
    for (int p = 0; p < PP; ++p) z += pp[(size_t)p * HWD] * w_s[p];
    g_att[idx] = 1.f / (1.f + expf(-z));
}

// ---------------- main GEMM: feats_part[p,c] += (pa*att)[p,k] x[c,k] ----------------
__global__ __launch_bounds__(NTHREADS)
void rfe_main_kernel(const float* __restrict__ x,
                     const float* __restrict__ pa)
{
    __shared__ __align__(16) float pa_s[2][PP][PS];
    __shared__ __align__(16) float x_s[2][CT][PS];

    const int tid   = threadIdx.x;
    const int chunk = blockIdx.x;   // 0..6
    const int ct    = blockIdx.y;   // 0..1
    const int b     = blockIdx.z;   // 0..31
    const int hw0   = chunk * CHUNK;

    // gmem load mapping: 8 float4 per row of KT floats
    const int kq  = tid & 7;   // which float4 within the k-tile
    const int row = tid >> 3;  // 0..15
    const float* xg = x  + ((size_t)b * CC + (size_t)ct * CT) * HWD + hw0 + kq * 4;
    const float* pg = pa + ((size_t)b * PP) * HWD + hw0 + kq * 4;
    const float* ag = g_att + (size_t)b * HWD + hw0 + kq * 4;

    // compute mapping: 4 p-groups x 32 c-lanes; per-thread tile 8p x 4c interleaved
    const int p_idx = tid >> 5;   // constant within warp -> pa smem broadcast
    const int c_idx = tid & 31;

    unsigned long long acc[8][4];
    #pragma unroll
    for (int i = 0; i < 8; ++i)
        #pragma unroll
        for (int j = 0; j < 4; ++j) acc[i][j] = 0ull;

    // ---- prologue: regs for pa/att tile 0, cp.async x tile 0 ----
    float4 pa_r[2], att_r;
    #pragma unroll
    for (int r = 0; r < 2; ++r)
        pa_r[r] = *(const float4*)(pg + (size_t)(row + 16 * r) * HWD);
    att_r = *(const float4*)(ag);
    #pragma unroll
    for (int r = 0; r < 8; ++r)
        cpasync16(__cvta_generic_to_shared(&x_s[0][row + 16 * r][kq * 4]),
                  xg + (size_t)(row + 16 * r) * HWD);
    cpcommit();

    for (int t = 0; t < NKT; ++t) {
        const int cbuf = t & 1, nbuf = (t + 1) & 1;

        if (t + 1 < NKT) {
            const int kn = (t + 1) * KT;
            #pragma unroll
            for (int r = 0; r < 8; ++r)
                cpasync16(__cvta_generic_to_shared(&x_s[nbuf][row + 16 * r][kq * 4]),
                          xg + (size_t)(row + 16 * r) * HWD + kn);
            cpcommit();
        }

        // store gated pa tile t (regs -> smem), fold att
        #pragma unroll
        for (int r = 0; r < 2; ++r) {
            float4 v = pa_r[r];
            v.x *= att_r.x; v.y *= att_r.y; v.z *= att_r.z; v.w *= att_r.w;
            *(float4*)&pa_s[cbuf][row + 16 * r][kq * 4] = v;
        }

        // prefetch pa/att regs for tile t+1
        if (t + 1 < NKT) {
            const int kn = (t + 1) * KT;
            #pragma unroll
            for (int r = 0; r < 2; ++r)
                pa_r[r] = *(const float4*)(pg + (size_t)(row + 16 * r) * HWD + kn);
            att_r = *(const float4*)(ag + kn);
        }

        if (t + 1 < NKT) cpwait<1>(); else cpwait<0>();
        __syncthreads();

        // GEMM on buffer cbuf: packed f32x2 over k-pairs
        #pragma unroll
        for (int k = 0; k < KT; k += 4) {
            ulonglong2 xv[4];
            #pragma unroll
            for (int j = 0; j < 4; ++j)
                xv[j] = *(const ulonglong2*)&x_s[cbuf][c_idx + 32 * j][k];
            #pragma unroll
            for (int i = 0; i < 8; ++i) {
                const ulonglong2 av = *(const ulonglong2*)&pa_s[cbuf][p_idx + 4 * i][k];
                #pragma unroll
                for (int j = 0; j < 4; ++j) {
                    FMA2(acc[i][j], av.x, xv[j].x);
                    FMA2(acc[i][j], av.y, xv[j].y);
                }
            }
        }
        __syncthreads();
    }

    // write partial [chunk][b][p][c]
    float* outp = g_part + ((size_t)chunk * BB + b) * (PP * CC);
    #pragma unroll
    for (int i = 0; i < 8; ++i) {
        const int p = p_idx + 4 * i;
        #pragma unroll
        for (int j = 0; j < 4; ++j) {
            const int c = ct * CT + c_idx + 32 * j;
            const unsigned long long v = acc[i][j];
            const float lo = __uint_as_float((unsigned)(v & 0xffffffffull));
            const float hi = __uint_as_float((unsigned)(v >> 32));
            outp[p * CC + c] = lo + hi;
        }
    }
}

// ---------------- split-K reduce, vectorized ----------------
__global__ __launch_bounds__(256)
void rfe_reduce_kernel(float4* __restrict__ out)
{
    const int idx = blockIdx.x * 256 + threadIdx.x;   // 0..65535
    const float4* gp = (const float4*)g_part;
    float4 s = gp[idx];
    #pragma unroll
    for (int ch = 1; ch < NCH; ++ch) {
        float4 v = gp[(size_t)ch * (BB * PP * CC / 4) + idx];
        s.x += v.x; s.y += v.y; s.z += v.z; s.w += v.w;
    }
    out[idx] = s;
}

extern "C" void kernel_launch(void* const* d_in, const int* in_sizes, int n_in,
                              void* d_out, int out_size)
{
    const float* x      = (const float*)d_in[0];  // [32,256,56,56]
    const float* pa     = (const float*)d_in[1];  // [32,32,56,56]
    const float* conv_w = (const float*)d_in[2];  // [32]
    const float* conv_b = (const float*)d_in[3];  // [1]
    float* out = (float*)d_out;                   // [32, 8192]

    rfe_att_kernel<<<(BB * HWD) / 256, 256>>>(pa, conv_w, conv_b);
    dim3 grid(NCH, NCT, BB);
    rfe_main_kernel<<<grid, NTHREADS>>>(x, pa);
    rfe_reduce_kernel<<<(BB * PP * CC) / 1024, 256>>>((float4*)out);
}